// round 15
// baseline (speedup 1.0000x reference)
#include <cuda_runtime.h>
#include <cuda_bf16.h>
#include <cfloat>
#include <cstdint>

#define HIDDEN    1024
#define NUM_HEADS 16
#define HEAD_DIM  64
#define BATCH     32
#define PREV_LEN  4095
#define SEQ       4096
#define SCALING   0.125f
#define NH_TOT    (BATCH * NUM_HEADS)   // 512

__device__ float g_q[BATCH * HIDDEN];
__device__ float g_k[BATCH * HIDDEN];
__device__ float g_v[BATCH * HIDDEN];
// per-half unnormalized attention partials: index [half*512 + n]
__device__ float g_fm[2 * NH_TOT];
__device__ float g_fl[2 * NH_TOT];
__device__ float g_facc[2 * NH_TOT * HEAD_DIM];
// slot-pair group table (built by q_kernel block 0)
__device__ int g_gb0[BATCH];
__device__ int g_gb1[BATCH];

__device__ __forceinline__ float dot4(float4 a, float4 b) {
    return a.x*b.x + a.y*b.y + a.z*b.z + a.w*b.w;
}

__device__ __forceinline__ void pdl_trigger() {
    asm volatile("griddepcontrol.launch_dependents;");
}
__device__ __forceinline__ void pdl_wait() {
    asm volatile("griddepcontrol.wait;");
}

#define GEMM_SMEM (8 * 1024 * 4)

// ---------------------------------------------------------------------------
// Deep-prefetch GEMM (2 cols/warp, 16 LDG.128 up-front).
// ---------------------------------------------------------------------------
__device__ __forceinline__ void gemm_prefetch(
    const float* __restrict__ W, int j0, int lane, float4* wa, float4* wb)
{
    const float* Wa = W + (size_t)j0 * 1024 + lane * 4;
    const float* Wb = Wa + 1024;
    #pragma unroll
    for (int it = 0; it < 8; it++) {
        wa[it] = *(const float4*)(Wa + it * 128);
        wb[it] = *(const float4*)(Wb + it * 128);
    }
}

__device__ __forceinline__ void gemm_core(
    const float4* wa, const float4* wb,
    const float* __restrict__ bias, float* __restrict__ out,
    float scale, int row0, int j0, const float* Xs)
{
    int lane = threadIdx.x & 31;

    float acc[16];
    #pragma unroll
    for (int i = 0; i < 16; i++) acc[i] = 0.f;

    #pragma unroll
    for (int it = 0; it < 8; it++) {
        const float* xb = Xs + it * 128 + lane * 4;
        #pragma unroll
        for (int r = 0; r < 8; r++) {
            float4 x4 = *(const float4*)(xb + (r << 10));
            acc[r]     += dot4(x4, wa[it]);
            acc[8 + r] += dot4(x4, wb[it]);
        }
    }

    #pragma unroll
    for (int i = 0; i < 16; i++)
        acc[i] += __shfl_xor_sync(0xffffffffu, acc[i], 16);
    #pragma unroll
    for (int off = 8; off; off >>= 1) {
        #pragma unroll
        for (int i = 0; i < off; i++) {
            bool hi = (lane & off) != 0;
            float z = hi ? acc[i] : acc[i + off];
            z = __shfl_xor_sync(0xffffffffu, z, off);
            acc[i] = (hi ? acc[i + off] : acc[i]) + z;
        }
    }

    if (lane < 16) {
        int c = lane >> 3, r = lane & 7;
        int j = j0 + c;
        out[(row0 + r) * 1024 + j] = (acc[0] + bias[j]) * scale;
    }
}

// Register-light GEMM for the kv branch of the fused kernel.
__device__ __forceinline__ void gemm_compute_lite(
    const float* __restrict__ W, const float* __restrict__ bias,
    float* __restrict__ out, float scale, int row0, int colblk,
    const float* Xs)
{
    int warp = threadIdx.x >> 5;
    int lane = threadIdx.x & 31;
    int j0 = colblk * 16 + warp * 2;

    const float* Wa = W + (size_t)j0 * 1024;
    const float* Wb = Wa + 1024;

    float acc[16];
    #pragma unroll
    for (int i = 0; i < 16; i++) acc[i] = 0.f;

    float4 wa = *(const float4*)(Wa + lane * 4);
    float4 wb = *(const float4*)(Wb + lane * 4);

    #pragma unroll
    for (int it = 0; it < 8; it++) {
        int k0 = it * 128 + lane * 4;
        float4 ca = wa, cb = wb;
        if (it < 7) {
            wa = *(const float4*)(Wa + k0 + 128);
            wb = *(const float4*)(Wb + k0 + 128);
        }
        const float* xb = Xs + k0;
        #pragma unroll
        for (int r = 0; r < 8; r++) {
            float4 x4 = *(const float4*)(xb + (r << 10));
            acc[r]     += dot4(x4, ca);
            acc[8 + r] += dot4(x4, cb);
        }
    }

    #pragma unroll
    for (int i = 0; i < 16; i++)
        acc[i] += __shfl_xor_sync(0xffffffffu, acc[i], 16);
    #pragma unroll
    for (int off = 8; off; off >>= 1) {
        #pragma unroll
        for (int i = 0; i < off; i++) {
            bool hi = (lane & off) != 0;
            float z = hi ? acc[i] : acc[i + off];
            z = __shfl_xor_sync(0xffffffffu, z, off);
            acc[i] = (hi ? acc[i + off] : acc[i]) + z;
        }
    }

    if (lane < 16) {
        int c = lane >> 3, r = lane & 7;
        int j = j0 + c;
        out[(row0 + r) * 1024 + j] = (acc[0] + bias[j]) * scale;
    }
}

__device__ __forceinline__ void gemm_stage_x(const float* __restrict__ X,
                                             int row0, float* Xs)
{
    const float4* X4 = (const float4*)(X + row0 * 1024);
    float4* Xs4 = (float4*)Xs;
    for (int idx = threadIdx.x; idx < 8 * 1024 / 4; idx += 256)
        Xs4[idx] = X4[idx];
    __syncthreads();
}

// ---------------------------------------------------------------------------
// q projection + (block 0) slot-pair group table construction.
// ---------------------------------------------------------------------------
__global__ __launch_bounds__(256) void q_kernel(
    const float* __restrict__ Xq, const float* __restrict__ Wq,
    const float* __restrict__ bq, float* __restrict__ oq,
    const int* __restrict__ order)
{
    extern __shared__ float Xs[];
    __shared__ int s_ord[BATCH];
    __shared__ int s_g[BATCH];

    if (blockIdx.x == 0 && threadIdx.x < 32) {
        int tid = threadIdx.x;
        g_gb0[tid] = -1;
        g_gb1[tid] = -1;
        s_ord[tid] = order[tid];
        __syncwarp();
        int c = s_ord[tid];
        int cnt = 0;
        #pragma unroll
        for (int b2 = 0; b2 < BATCH; b2++) cnt += (s_ord[b2] == tid);
        s_g[tid] = (cnt + 1) >> 1;
        __syncwarp();
        int r = 0;
        #pragma unroll
        for (int b2 = 0; b2 < BATCH; b2++) r += (b2 < tid && s_ord[b2] == c);
        int base = 0;
        #pragma unroll
        for (int c2 = 0; c2 < BATCH; c2++) base += (c2 < c) ? s_g[c2] : 0;
        int gid = base + (r >> 1);
        __syncwarp();
        if ((r & 1) == 0) g_gb0[gid] = tid; else g_gb1[gid] = tid;
    }

    int rt = blockIdx.x >> 6;
    int cb = blockIdx.x & 63;
    int warp = threadIdx.x >> 5;
    int lane = threadIdx.x & 31;
    int j0 = cb * 16 + warp * 2;

    float4 wa[8], wb[8];
    gemm_prefetch(Wq, j0, lane, wa, wb);
    gemm_stage_x(Xq, rt * 8, Xs);
    gemm_core(wa, wb, bq, oq, SCALING, rt * 8, j0, Xs);
    pdl_trigger();
}

// ---------------------------------------------------------------------------
// Split-KV streaming core over one half (2048 positions), NQ queries.
// base = half*2048. All shuffles unconditional; final iter peeled for the
// (half==1, hw==15) out-of-range position s==4095.
// ---------------------------------------------------------------------------
template<int NQ>
__device__ __forceinline__ void attn_stream_half(
    const float* __restrict__ Kc, const float* __restrict__ Vc,
    const float* s_mask, int base, int hw, int sl,
    const float4* q, float* m, float* l, float4* A)
{
    #pragma unroll 4
    for (int it = 0; it < 127; it++) {
        int s = base + (it << 4) + hw;
        const float* kp = Kc + (size_t)s * HEAD_DIM + sl * 4;
        const float* vp = Vc + (size_t)s * HEAD_DIM + sl * 4;
        float4 k4 = *(const float4*)kp;
        float4 v4 = *(const float4*)vp;
        float maskv = s_mask[s];

        float p[NQ];
        #pragma unroll
        for (int j = 0; j < NQ; j++) p[j] = dot4(q[j], k4);
        #pragma unroll
        for (int j = 0; j < NQ; j++) p[j] += __shfl_xor_sync(0xffffffffu, p[j], 8);
        #pragma unroll
        for (int j = 0; j < NQ; j++) p[j] += __shfl_xor_sync(0xffffffffu, p[j], 4);
        #pragma unroll
        for (int j = 0; j < NQ; j++) p[j] += __shfl_xor_sync(0xffffffffu, p[j], 2);
        #pragma unroll
        for (int j = 0; j < NQ; j++) p[j] += __shfl_xor_sync(0xffffffffu, p[j], 1);

        #pragma unroll
        for (int j = 0; j < NQ; j++) {
            float score = p[j] - maskv;
            float nm = fmaxf(m[j], score);
            float es = __expf(m[j] - nm);
            float w  = __expf(score - nm);
            l[j] = l[j] * es + w;
            A[j].x = A[j].x * es + w * v4.x;
            A[j].y = A[j].y * es + w * v4.y;
            A[j].z = A[j].z * es + w * v4.z;
            A[j].w = A[j].w * es + w * v4.w;
            m[j] = nm;
        }
    }

    // peeled final iteration
    {
        int s = base + (127 << 4) + hw;
        bool valid = s < PREV_LEN;
        int sc = valid ? s : 0;
        const float* kp = Kc + (size_t)sc * HEAD_DIM + sl * 4;
        const float* vp = Vc + (size_t)sc * HEAD_DIM + sl * 4;
        float4 k4 = *(const float4*)kp;
        float4 v4 = *(const float4*)vp;

        float p[NQ];
        #pragma unroll
        for (int j = 0; j < NQ; j++) p[j] = dot4(q[j], k4);
        #pragma unroll
        for (int j = 0; j < NQ; j++) p[j] += __shfl_xor_sync(0xffffffffu, p[j], 8);
        #pragma unroll
        for (int j = 0; j < NQ; j++) p[j] += __shfl_xor_sync(0xffffffffu, p[j], 4);
        #pragma unroll
        for (int j = 0; j < NQ; j++) p[j] += __shfl_xor_sync(0xffffffffu, p[j], 2);
        #pragma unroll
        for (int j = 0; j < NQ; j++) p[j] += __shfl_xor_sync(0xffffffffu, p[j], 1);

        if (valid) {
            float maskv = s_mask[s];
            #pragma unroll
            for (int j = 0; j < NQ; j++) {
                float score = p[j] - maskv;
                float nm = fmaxf(m[j], score);
                float es = __expf(m[j] - nm);
                float w  = __expf(score - nm);
                l[j] = l[j] * es + w;
                A[j].x = A[j].x * es + w * v4.x;
                A[j].y = A[j].y * es + w * v4.y;
                A[j].z = A[j].z * es + w * v4.z;
                A[j].w = A[j].w * es + w * v4.w;
                m[j] = nm;
            }
        }
    }
}

// combine 16 half-warp partials -> write g_f*(slot = half*512 + n)
__device__ __forceinline__ void attn_combine_write(
    const float4* s_acc, const float* s_m, const float* s_l,
    int tid, int slot)
{
    if (tid < HEAD_DIM) {
        float M = s_m[0];
        #pragma unroll
        for (int w = 1; w < 16; w++) M = fmaxf(M, s_m[w]);
        float L = 0.f, A = 0.f;
        #pragma unroll
        for (int w = 0; w < 16; w++) {
            float f = __expf(s_m[w] - M);
            L += s_l[w] * f;
            A += ((const float*)(s_acc + w * 16))[tid] * f;
        }
        g_facc[slot * HEAD_DIM + tid] = A;
        if (tid == 0) { g_fm[slot] = M; g_fl[slot] = L; }
    }
}

// ---------------------------------------------------------------------------
// Fused kernel (PDL secondary of q).
// Blocks 0..1023: attention (grp 0..31, half 0..1, head 0..15) — each block
// streams ONE HALF of one cache slot for 1 or 2 batch rows sharing it.
// ~717 active streaming blocks; empty groups exit. Blocks 1024..1535: kv
// projection backfill (never wait on q).
// ---------------------------------------------------------------------------
__global__ __launch_bounds__(256) void attn_kv_kernel(
    const float* __restrict__ prev_key, const float* __restrict__ prev_value,
    const int*  __restrict__ order,     const int* __restrict__ mask,
    const float* __restrict__ Xk, const float* __restrict__ Xv,
    const float* __restrict__ Wk, const float* __restrict__ bk,
    const float* __restrict__ Wv, const float* __restrict__ bv,
    float* __restrict__ ok, float* __restrict__ ov)
{
    extern __shared__ float smemBuf[];

    if (blockIdx.x >= 1024) {
        int blk = blockIdx.x - 1024;      // p*256 + rt*64 + cb
        int p   = blk >> 8;
        int rt  = (blk >> 6) & 3;
        int cb  = blk & 63;
        if (p == 0) {
            gemm_stage_x(Xk, rt * 8, smemBuf);
            gemm_compute_lite(Wk, bk, ok, 1.0f, rt * 8, cb, smemBuf);
        } else {
            gemm_stage_x(Xv, rt * 8, smemBuf);
            gemm_compute_lite(Wv, bv, ov, 1.0f, rt * 8, cb, smemBuf);
        }
        pdl_trigger();
        return;
    }

    // ---- attention blocks ----
    float* s_mask = smemBuf;                       // [4096]
    float* s_m    = smemBuf + SEQ;                 // [16]
    float* s_l    = s_m + 16;                      // [16]
    float4* s_acc = (float4*)(s_l + 16);           // [16][16]

    int tid = threadIdx.x;
    int hw  = tid >> 4;
    int sl  = tid & 15;

    int grp  = blockIdx.x >> 5;
    int half = (blockIdx.x >> 4) & 1;
    int h    = blockIdx.x & 15;
    int base = half << 11;                 // 0 or 2048

    // pre-wait: stage only this half's mask region + tail guard usage
    for (int idx = tid; idx < SEQ; idx += 256)
        s_mask[idx] = FLT_MAX * (float)mask[idx];
    __syncthreads();

    pdl_wait();

    int b0 = g_gb0[grp];
    if (b0 < 0) { pdl_trigger(); return; }
    int b1 = g_gb1[grp];

    int ob = order[b0];
    size_t cache_base = ((size_t)(ob * NUM_HEADS + h)) * PREV_LEN * HEAD_DIM;
    const float* Kc = prev_key   + cache_base;
    const float* Vc = prev_value + cache_base;

    if (b1 >= 0) {
        float4 q[2];
        q[0] = *(const float4*)(g_q + b0 * HIDDEN + h * HEAD_DIM + sl * 4);
        q[1] = *(const float4*)(g_q + b1 * HIDDEN + h * HEAD_DIM + sl * 4);
        float m[2] = { -FLT_MAX, -FLT_MAX };
        float l[2] = { 0.f, 0.f };
        float4 A[2] = { make_float4(0.f,0.f,0.f,0.f), make_float4(0.f,0.f,0.f,0.f) };

        attn_stream_half<2>(Kc, Vc, s_mask, base, hw, sl, q, m, l, A);

        s_acc[hw * 16 + sl] = A[0];
        if (sl == 0) { s_m[hw] = m[0]; s_l[hw] = l[0]; }
        __syncthreads();
        attn_combine_write(s_acc, s_m, s_l, tid,
                           half * NH_TOT + b0 * NUM_HEADS + h);
        __syncthreads();
        s_acc[hw * 16 + sl] = A[1];
        if (sl == 0) { s_m[hw] = m[1]; s_l[hw] = l[1]; }
        __syncthreads();
        attn_combine_write(s_acc, s_m, s_l, tid,
                           half * NH_TOT + b1 * NUM_HEADS + h);
    } else {
        float4 q[1];
        q[0] = *(const float4*)(g_q + b0 * HIDDEN + h * HEAD_DIM + sl * 4);
        float m[1] = { -FLT_MAX };
        float l[1] = { 0.f };
        float4 A[1] = { make_float4(0.f,0.f,0.f,0.f) };

        attn_stream_half<1>(Kc, Vc, s_mask, base, hw, sl, q, m, l, A);

        s_acc[hw * 16 + sl] = A[0];
        if (sl == 0) { s_m[hw] = m[0]; s_l[hw] = l[0]; }
        __syncthreads();
        attn_combine_write(s_acc, s_m, s_l, tid,
                           half * NH_TOT + b0 * NUM_HEADS + h);
    }
    pdl_trigger();
}

// ---------------------------------------------------------------------------
// oproj + 3-way merge (half0, half1, fresh position).  256 blocks.
// ---------------------------------------------------------------------------
__global__ __launch_bounds__(256) void oproj_merge_kernel(
    const int* __restrict__ mask,
    const float* __restrict__ W, const float* __restrict__ bias,
    float* __restrict__ out)
{
    extern __shared__ float Xs[];
    __shared__ float s_e0[8 * 16];
    __shared__ float s_e1[8 * 16];
    __shared__ float s_w [8 * 16];

    int rt = blockIdx.x >> 6;
    int cb = blockIdx.x & 63;
    int row0 = rt * 8;
    int tid = threadIdx.x;
    int warp = tid >> 5;
    int lane = tid & 31;
    int j0 = cb * 16 + warp * 2;

    float4 wa[8], wb[8];
    gemm_prefetch(W, j0, lane, wa, wb);

    pdl_wait();

    if (tid < 128) {
        int r = tid >> 4, h = tid & 15;
        int b = row0 + r;
        int n = b * NUM_HEADS + h;
        int qbase = b * HIDDEN + h * HEAD_DIM;

        float p = 0.f;
        #pragma unroll
        for (int i = 0; i < HEAD_DIM; i += 4) {
            float4 qq = *(const float4*)(g_q + qbase + i);   // pre-scaled
            float4 kk = *(const float4*)(g_k + qbase + i);
            p += dot4(qq, kk);
        }
        float score = p - FLT_MAX * (float)mask[PREV_LEN];
        float m0 = g_fm[n],         l0 = g_fl[n];
        float m1 = g_fm[NH_TOT + n], l1 = g_fl[NH_TOT + n];
        float M = fmaxf(fmaxf(m0, m1), score);
        float e0 = __expf(m0 - M);
        float e1 = __expf(m1 - M);
        float w  = __expf(score - M);
        float L  = l0 * e0 + l1 * e1 + w;
        s_e0[tid] = e0 / L;
        s_e1[tid] = e1 / L;
        s_w[tid]  = w  / L;
    }
    __syncthreads();

    for (int idx4 = tid; idx4 < 8 * 256; idx4 += 256) {
        int r    = idx4 >> 8;
        int c4   = idx4 & 255;
        int h    = c4 >> 4;
        int rh   = r * 16 + h;
        float e0L = s_e0[rh], e1L = s_e1[rh], wL = s_w[rh];
        int b = row0 + r;
        int n = b * NUM_HEADS + h;
        int d4 = c4 & 15;
        float4 f0 = *(const float4*)(g_facc + (size_t)n * HEAD_DIM + d4 * 4);
        float4 f1 = *(const float4*)(g_facc + (size_t)(NH_TOT + n) * HEAD_DIM + d4 * 4);
        float4 vv = *(const float4*)(g_v + b * HIDDEN + c4 * 4);
        float4 x;
        x.x = f0.x * e0L + f1.x * e1L + vv.x * wL;
        x.y = f0.y * e0L + f1.y * e1L + vv.y * wL;
        x.z = f0.z * e0L + f1.z * e1L + vv.z * wL;
        x.w = f0.w * e0L + f1.w * e1L + vv.w * wL;
        ((float4*)Xs)[idx4] = x;
    }
    __syncthreads();

    gemm_core(wa, wb, bias, out, 1.0f, row0, j0, Xs);
}

// ---------------------------------------------------------------------------
extern "C" void kernel_launch(void* const* d_in, const int* in_sizes, int n_in,
                              void* d_out, int out_size)
{
    const float* qin  = (const float*)d_in[0];
    const float* kin  = (const float*)d_in[1];
    const float* vin  = (const float*)d_in[2];
    const int*   mask = (const int*)  d_in[3];
    const int*   ord  = (const int*)  d_in[4];
    const float* pk   = (const float*)d_in[5];
    const float* pv   = (const float*)d_in[6];
    const float* Wq   = (const float*)d_in[7];
    const float* bq   = (const float*)d_in[8];
    const float* Wk   = (const float*)d_in[9];
    const float* bk   = (const float*)d_in[10];
    const float* Wv   = (const float*)d_in[11];
    const float* bv   = (const float*)d_in[12];
    const float* Wo   = (const float*)d_in[13];
    const float* bo   = (const float*)d_in[14];
    float* out = (float*)d_out;

    float *gq, *gk, *gv;
    cudaGetSymbolAddress((void**)&gq, g_q);
    cudaGetSymbolAddress((void**)&gk, g_k);
    cudaGetSymbolAddress((void**)&gv, g_v);

    // 1) q projection + group-table build
    q_kernel<<<256, 256, GEMM_SMEM>>>(qin, Wq, bq, gq, ord);

    // 2) attn (split-KV slot-pair dedup) + kv backfill, PDL after q
    {
        cudaLaunchConfig_t cfg = {};
        cfg.gridDim  = dim3(1536, 1, 1);
        cfg.blockDim = dim3(256, 1, 1);
        cfg.dynamicSmemBytes = GEMM_SMEM;
        cfg.stream = 0;
        cudaLaunchAttribute at[1];
        at[0].id = cudaLaunchAttributeProgrammaticStreamSerialization;
        at[0].val.programmaticStreamSerializationAllowed = 1;
        cfg.attrs = at;
        cfg.numAttrs = 1;
        cudaLaunchKernelEx(&cfg, attn_kv_kernel, pk, pv, ord, mask,
                           kin, vin, Wk, bk, Wv, bv, gk, gv);
    }

    // 3) oproj + 3-way merge, PDL after attn_kv
    {
        cudaLaunchConfig_t cfg = {};
        cfg.gridDim  = dim3(256, 1, 1);
        cfg.blockDim = dim3(256, 1, 1);
        cfg.dynamicSmemBytes = GEMM_SMEM;
        cfg.stream = 0;
        cudaLaunchAttribute at[1];
        at[0].id = cudaLaunchAttributeProgrammaticStreamSerialization;
        at[0].val.programmaticStreamSerializationAllowed = 1;
        cfg.attrs = at;
        cfg.numAttrs = 1;
        cudaLaunchKernelEx(&cfg, oproj_merge_kernel, mask, Wo, bo, out);
    }
}

// round 16
// speedup vs baseline: 1.6280x; 1.6280x over previous
#include <cuda_runtime.h>
#include <cuda_bf16.h>
#include <cfloat>
#include <cstdint>

#define HIDDEN    1024
#define NUM_HEADS 16
#define HEAD_DIM  64
#define BATCH     32
#define PREV_LEN  4095
#define SEQ       4096
#define SCALING   0.125f

__device__ float g_q[BATCH * HIDDEN];
__device__ float g_k[BATCH * HIDDEN];
__device__ float g_v[BATCH * HIDDEN];
// unnormalized attention partials over the 4095 cached positions
__device__ float g_fm[BATCH * NUM_HEADS];
__device__ float g_fl[BATCH * NUM_HEADS];
__device__ float g_facc[BATCH * NUM_HEADS * HEAD_DIM];

__device__ __forceinline__ float dot4(float4 a, float4 b) {
    return a.x*b.x + a.y*b.y + a.z*b.z + a.w*b.w;
}

__device__ __forceinline__ void pdl_trigger() {
    asm volatile("griddepcontrol.launch_dependents;");
}
__device__ __forceinline__ void pdl_wait() {
    asm volatile("griddepcontrol.wait;");
}

#define GEMM_SMEM (8 * 1024 * 4)

// ---------------------------------------------------------------------------
// Deep-prefetch GEMM (2 cols/warp, 16 LDG.128 up-front).
// ---------------------------------------------------------------------------
__device__ __forceinline__ void gemm_prefetch(
    const float* __restrict__ W, int j0, int lane, float4* wa, float4* wb)
{
    const float* Wa = W + (size_t)j0 * 1024 + lane * 4;
    const float* Wb = Wa + 1024;
    #pragma unroll
    for (int it = 0; it < 8; it++) {
        wa[it] = *(const float4*)(Wa + it * 128);
        wb[it] = *(const float4*)(Wb + it * 128);
    }
}

__device__ __forceinline__ void gemm_core(
    const float4* wa, const float4* wb,
    const float* __restrict__ bias, float* __restrict__ out,
    float scale, int row0, int j0, const float* Xs)
{
    int lane = threadIdx.x & 31;

    float acc[16];
    #pragma unroll
    for (int i = 0; i < 16; i++) acc[i] = 0.f;

    #pragma unroll
    for (int it = 0; it < 8; it++) {
        const float* xb = Xs + it * 128 + lane * 4;
        #pragma unroll
        for (int r = 0; r < 8; r++) {
            float4 x4 = *(const float4*)(xb + (r << 10));
            acc[r]     += dot4(x4, wa[it]);
            acc[8 + r] += dot4(x4, wb[it]);
        }
    }

    #pragma unroll
    for (int i = 0; i < 16; i++)
        acc[i] += __shfl_xor_sync(0xffffffffu, acc[i], 16);
    #pragma unroll
    for (int off = 8; off; off >>= 1) {
        #pragma unroll
        for (int i = 0; i < off; i++) {
            bool hi = (lane & off) != 0;
            float z = hi ? acc[i] : acc[i + off];
            z = __shfl_xor_sync(0xffffffffu, z, off);
            acc[i] = (hi ? acc[i + off] : acc[i]) + z;
        }
    }

    if (lane < 16) {
        int c = lane >> 3, r = lane & 7;
        int j = j0 + c;
        out[(row0 + r) * 1024 + j] = (acc[0] + bias[j]) * scale;
    }
}

// Register-light GEMM for the kv branch of the fused kernel.
__device__ __forceinline__ void gemm_compute_lite(
    const float* __restrict__ W, const float* __restrict__ bias,
    float* __restrict__ out, float scale, int row0, int colblk,
    const float* Xs)
{
    int warp = threadIdx.x >> 5;
    int lane = threadIdx.x & 31;
    int j0 = colblk * 16 + warp * 2;

    const float* Wa = W + (size_t)j0 * 1024;
    const float* Wb = Wa + 1024;

    float acc[16];
    #pragma unroll
    for (int i = 0; i < 16; i++) acc[i] = 0.f;

    float4 wa = *(const float4*)(Wa + lane * 4);
    float4 wb = *(const float4*)(Wb + lane * 4);

    #pragma unroll
    for (int it = 0; it < 8; it++) {
        int k0 = it * 128 + lane * 4;
        float4 ca = wa, cb = wb;
        if (it < 7) {
            wa = *(const float4*)(Wa + k0 + 128);
            wb = *(const float4*)(Wb + k0 + 128);
        }
        const float* xb = Xs + k0;
        #pragma unroll
        for (int r = 0; r < 8; r++) {
            float4 x4 = *(const float4*)(xb + (r << 10));
            acc[r]     += dot4(x4, ca);
            acc[8 + r] += dot4(x4, cb);
        }
    }

    #pragma unroll
    for (int i = 0; i < 16; i++)
        acc[i] += __shfl_xor_sync(0xffffffffu, acc[i], 16);
    #pragma unroll
    for (int off = 8; off; off >>= 1) {
        #pragma unroll
        for (int i = 0; i < off; i++) {
            bool hi = (lane & off) != 0;
            float z = hi ? acc[i] : acc[i + off];
            z = __shfl_xor_sync(0xffffffffu, z, off);
            acc[i] = (hi ? acc[i + off] : acc[i]) + z;
        }
    }

    if (lane < 16) {
        int c = lane >> 3, r = lane & 7;
        int j = j0 + c;
        out[(row0 + r) * 1024 + j] = (acc[0] + bias[j]) * scale;
    }
}

__device__ __forceinline__ void gemm_stage_x(const float* __restrict__ X,
                                             int row0, float* Xs)
{
    const float4* X4 = (const float4*)(X + row0 * 1024);
    float4* Xs4 = (float4*)Xs;
    for (int idx = threadIdx.x; idx < 8 * 1024 / 4; idx += 256)
        Xs4[idx] = X4[idx];
    __syncthreads();
}

// q projection (gates attention): 256 blocks; triggers PDL dependents.
__global__ __launch_bounds__(256) void q_kernel(
    const float* __restrict__ Xq, const float* __restrict__ Wq,
    const float* __restrict__ bq, float* __restrict__ oq)
{
    extern __shared__ float Xs[];
    int rt = blockIdx.x >> 6;
    int cb = blockIdx.x & 63;
    int warp = threadIdx.x >> 5;
    int lane = threadIdx.x & 31;
    int j0 = cb * 16 + warp * 2;

    float4 wa[8], wb[8];
    gemm_prefetch(Wq, j0, lane, wa, wb);
    gemm_stage_x(Xq, rt * 8, Xs);
    gemm_core(wa, wb, bq, oq, SCALING, rt * 8, j0, Xs);
    pdl_trigger();
}

// Single-MUFU online-softmax step: one of es/w is exactly 1 since
// nm = max(m, score).  Bit-identical to the two-__expf version.
__device__ __forceinline__ void softmax_step(
    float score, float& m, float& l, float4& acc, float4 v4)
{
    float d  = score - m;
    float t  = __expf(-fabsf(d));
    bool  gt = d > 0.f;
    float es = gt ? t : 1.f;
    float w  = gt ? 1.f : t;
    m = fmaxf(m, score);
    l = l * es + w;
    acc.x = acc.x * es + w * v4.x;
    acc.y = acc.y * es + w * v4.y;
    acc.z = acc.z * es + w * v4.z;
    acc.w = acc.w * es + w * v4.w;
}

// ---------------------------------------------------------------------------
// Fused kernel (PDL secondary of q): blocks 0..511 = attention over cached
// positions (pre-stage mask, then wait for q); blocks 512..1023 = k/v
// projection backfill (never wait — overlap q itself).
// ---------------------------------------------------------------------------
__global__ __launch_bounds__(256) void attn_kv_kernel(
    const float* __restrict__ prev_key, const float* __restrict__ prev_value,
    const int*  __restrict__ order,     const int* __restrict__ mask,
    const float* __restrict__ Xk, const float* __restrict__ Xv,
    const float* __restrict__ Wk, const float* __restrict__ bk,
    const float* __restrict__ Wv, const float* __restrict__ bv,
    float* __restrict__ ok, float* __restrict__ ov)
{
    extern __shared__ float smemBuf[];

    if (blockIdx.x >= 512) {
        int blk = blockIdx.x - 512;       // p*256 + rt*64 + cb
        int p   = blk >> 8;
        int rt  = (blk >> 6) & 3;
        int cb  = blk & 63;
        if (p == 0) {
            gemm_stage_x(Xk, rt * 8, smemBuf);
            gemm_compute_lite(Wk, bk, ok, 1.0f, rt * 8, cb, smemBuf);
        } else {
            gemm_stage_x(Xv, rt * 8, smemBuf);
            gemm_compute_lite(Wv, bv, ov, 1.0f, rt * 8, cb, smemBuf);
        }
        pdl_trigger();
        return;
    }

    // ---- attention blocks ----
    float* s_mask = smemBuf;                       // [4096]
    float* s_m    = smemBuf + SEQ;                 // [16]
    float* s_l    = s_m + 16;                      // [16]
    float4* s_acc = (float4*)(s_l + 16);           // [16][16]

    int tid = threadIdx.x;
    int hw  = tid >> 4;
    int sl  = tid & 15;

    int n = blockIdx.x;
    int b = n >> 4;
    int h = n & 15;

    // pre-wait work: mask staging (input only, not q-dependent)
    for (int idx = tid; idx < SEQ; idx += 256)
        s_mask[idx] = FLT_MAX * (float)mask[idx];
    __syncthreads();

    int ob = order[b];
    size_t cache_base = ((size_t)(ob * NUM_HEADS + h)) * PREV_LEN * HEAD_DIM;
    const float* Kc = prev_key   + cache_base;
    const float* Vc = prev_value + cache_base;

    pdl_wait();

    int qbase = b * HIDDEN + h * HEAD_DIM;
    float4 q4 = *(const float4*)(g_q + qbase + sl * 4);

    float m = -FLT_MAX, l = 0.f;
    float4 acc = make_float4(0.f, 0.f, 0.f, 0.f);

    // iterations 0..254 always in bounds; deep unroll for MLP.
    #pragma unroll 8
    for (int it = 0; it < 255; it++) {
        int s = (it << 4) + hw;
        const float* kp = Kc + (size_t)s * HEAD_DIM + sl * 4;
        const float* vp = Vc + (size_t)s * HEAD_DIM + sl * 4;
        float4 k4 = *(const float4*)kp;
        float4 v4 = *(const float4*)vp;

        float p = dot4(q4, k4);
        p += __shfl_xor_sync(0xffffffffu, p, 8);
        p += __shfl_xor_sync(0xffffffffu, p, 4);
        p += __shfl_xor_sync(0xffffffffu, p, 2);
        p += __shfl_xor_sync(0xffffffffu, p, 1);

        softmax_step(p - s_mask[s], m, l, acc, v4);
    }

    // final iteration it=255: hw==15 (s=4095) out of range; all threads run
    // the shuffles (warp-converged), invalid lanes don't accumulate.
    {
        int s = (255 << 4) + hw;
        bool valid = s < PREV_LEN;
        int sc = valid ? s : 0;
        const float* kp = Kc + (size_t)sc * HEAD_DIM + sl * 4;
        const float* vp = Vc + (size_t)sc * HEAD_DIM + sl * 4;
        float4 k4 = *(const float4*)kp;
        float4 v4 = *(const float4*)vp;

        float p = dot4(q4, k4);
        p += __shfl_xor_sync(0xffffffffu, p, 8);
        p += __shfl_xor_sync(0xffffffffu, p, 4);
        p += __shfl_xor_sync(0xffffffffu, p, 2);
        p += __shfl_xor_sync(0xffffffffu, p, 1);

        if (valid)
            softmax_step(p - s_mask[s], m, l, acc, v4);
    }

    s_acc[hw * 16 + sl] = acc;
    if (sl == 0) { s_m[hw] = m; s_l[hw] = l; }
    __syncthreads();

    if (tid < HEAD_DIM) {
        float M = s_m[0];
        #pragma unroll
        for (int w = 1; w < 16; w++) M = fmaxf(M, s_m[w]);
        float L = 0.f, A = 0.f;
        #pragma unroll
        for (int w = 0; w < 16; w++) {
            float f = __expf(s_m[w] - M);
            L += s_l[w] * f;
            A += ((const float*)(s_acc + w * 16))[tid] * f;
        }
        g_facc[n * HEAD_DIM + tid] = A;
        if (tid == 0) { g_fm[n] = M; g_fl[n] = L; }
    }
    pdl_trigger();
}

// ---------------------------------------------------------------------------
// oproj + fused fresh-position merge (PDL secondary of attn_kv).  256 blocks.
// ---------------------------------------------------------------------------
__global__ __launch_bounds__(256) void oproj_merge_kernel(
    const int* __restrict__ mask,
    const float* __restrict__ W, const float* __restrict__ bias,
    float* __restrict__ out)
{
    extern __shared__ float Xs[];
    __shared__ float s_es[8 * 16];
    __shared__ float s_w [8 * 16];

    int rt = blockIdx.x >> 6;
    int cb = blockIdx.x & 63;
    int row0 = rt * 8;
    int tid = threadIdx.x;
    int warp = tid >> 5;
    int lane = tid & 31;
    int j0 = cb * 16 + warp * 2;

    // W prefetch overlaps the upstream attention kernel
    float4 wa[8], wb[8];
    gemm_prefetch(W, j0, lane, wa, wb);

    pdl_wait();

    if (tid < 128) {
        int r = tid >> 4, h = tid & 15;
        int b = row0 + r;
        int n = b * NUM_HEADS + h;
        int qbase = b * HIDDEN + h * HEAD_DIM;

        float p = 0.f;
        #pragma unroll
        for (int i = 0; i < HEAD_DIM; i += 4) {
            float4 qq = *(const float4*)(g_q + qbase + i);   // pre-scaled
            float4 kk = *(const float4*)(g_k + qbase + i);
            p += dot4(qq, kk);
        }
        float score = p - FLT_MAX * (float)mask[PREV_LEN];
        float m = g_fm[n], l = g_fl[n];
        float nm = fmaxf(m, score);
        float es = __expf(m - nm);
        float w  = __expf(score - nm);
        float L  = l * es + w;
        s_es[tid] = es / L;
        s_w[tid]  = w  / L;
    }
    __syncthreads();

    for (int idx4 = tid; idx4 < 8 * 256; idx4 += 256) {
        int r    = idx4 >> 8;
        int c4   = idx4 & 255;
        int h    = c4 >> 4;
        int rh   = r * 16 + h;
        float esL = s_es[rh], wL = s_w[rh];
        int b = row0 + r;
        int n = b * NUM_HEADS + h;
        int d4 = c4 & 15;
        float4 fa = *(const float4*)(g_facc + n * HEAD_DIM + d4 * 4);
        float4 vv = *(const float4*)(g_v + b * HIDDEN + c4 * 4);
        float4 x;
        x.x = fa.x * esL + vv.x * wL;
        x.y = fa.y * esL + vv.y * wL;
        x.z = fa.z * esL + vv.z * wL;
        x.w = fa.w * esL + vv.w * wL;
        ((float4*)Xs)[idx4] = x;
    }
    __syncthreads();

    gemm_core(wa, wb, bias, out, 1.0f, row0, j0, Xs);
}

// ---------------------------------------------------------------------------
extern "C" void kernel_launch(void* const* d_in, const int* in_sizes, int n_in,
                              void* d_out, int out_size)
{
    const float* qin  = (const float*)d_in[0];
    const float* kin  = (const float*)d_in[1];
    const float* vin  = (const float*)d_in[2];
    const int*   mask = (const int*)  d_in[3];
    const int*   ord  = (const int*)  d_in[4];
    const float* pk   = (const float*)d_in[5];
    const float* pv   = (const float*)d_in[6];
    const float* Wq   = (const float*)d_in[7];
    const float* bq   = (const float*)d_in[8];
    const float* Wk   = (const float*)d_in[9];
    const float* bk   = (const float*)d_in[10];
    const float* Wv   = (const float*)d_in[11];
    const float* bv   = (const float*)d_in[12];
    const float* Wo   = (const float*)d_in[13];
    const float* bo   = (const float*)d_in[14];
    float* out = (float*)d_out;

    float *gq, *gk, *gv;
    cudaGetSymbolAddress((void**)&gq, g_q);
    cudaGetSymbolAddress((void**)&gk, g_k);
    cudaGetSymbolAddress((void**)&gv, g_v);

    // 1) q projection
    q_kernel<<<256, 256, GEMM_SMEM>>>(qin, Wq, bq, gq);

    // 2) attn + kv, PDL-overlapped with q
    {
        cudaLaunchConfig_t cfg = {};
        cfg.gridDim  = dim3(1024, 1, 1);
        cfg.blockDim = dim3(256, 1, 1);
        cfg.dynamicSmemBytes = GEMM_SMEM;
        cfg.stream = 0;
        cudaLaunchAttribute at[1];
        at[0].id = cudaLaunchAttributeProgrammaticStreamSerialization;
        at[0].val.programmaticStreamSerializationAllowed = 1;
        cfg.attrs = at;
        cfg.numAttrs = 1;
        cudaLaunchKernelEx(&cfg, attn_kv_kernel, pk, pv, ord, mask,
                           kin, vin, Wk, bk, Wv, bv, gk, gv);
    }

    // 3) oproj + merge, PDL-overlapped with attn_kv
    {
        cudaLaunchConfig_t cfg = {};
        cfg.gridDim  = dim3(256, 1, 1);
        cfg.blockDim = dim3(256, 1, 1);
        cfg.dynamicSmemBytes = GEMM_SMEM;
        cfg.stream = 0;
        cudaLaunchAttribute at[1];
        at[0].id = cudaLaunchAttributeProgrammaticStreamSerialization;
        at[0].val.programmaticStreamSerializationAllowed = 1;
        cfg.attrs = at;
        cfg.numAttrs = 1;
        cudaLaunchKernelEx(&cfg, oproj_merge_kernel, mask, Wo, bo, out);
    }
}